// round 5
// baseline (speedup 1.0000x reference)
#include <cuda_runtime.h>
#include <cstdint>

#define B_   8
#define K_   19
#define C_   512
#define HW_  16384
#define SCH  1024                 // s-chunk staged in smem (per buffer)
#define NCHUNK (HW_ / SCH)        // 16
#define STEPS 16                  // steps per chunk per warp (32 s each, s-half of 512)
#define CT   32                   // c rows per block
#define NTHR 512                  // 16 warps = 8 c-quads x 2 s-halves
#define SMEM_FLOATS (2 * K_ * SCH)

typedef unsigned long long u64;

__device__ __align__(16) float g_e[B_ * K_ * HW_];
__device__ float g_inv[B_ * K_];

// ---------------------------------------------------------------------------
// Kernel 1: e = exp(p - rowmax), inv = 1/sum(e). One block per (b,k) row.
// ---------------------------------------------------------------------------
__global__ __launch_bounds__(256) void softmax_k(const float* __restrict__ probs) {
    const int row = blockIdx.x;
    const float4* p4 = (const float4*)(probs + (size_t)row * HW_);
    float4* e4 = (float4*)(g_e + (size_t)row * HW_);
    const int tid = threadIdx.x;

    float4 v[16];
    float m = -1e30f;
#pragma unroll
    for (int i = 0; i < 16; i++) {
        v[i] = p4[tid + 256 * i];
        m = fmaxf(m, fmaxf(fmaxf(v[i].x, v[i].y), fmaxf(v[i].z, v[i].w)));
    }

    __shared__ float red[32];
#pragma unroll
    for (int off = 16; off; off >>= 1) m = fmaxf(m, __shfl_xor_sync(0xffffffffu, m, off));
    if ((tid & 31) == 0) red[tid >> 5] = m;
    __syncthreads();
    if (tid < 32) {
        float t = (tid < 8) ? red[tid] : -1e30f;
#pragma unroll
        for (int off = 4; off; off >>= 1) t = fmaxf(t, __shfl_xor_sync(0xffffffffu, t, off));
        if (tid == 0) red[0] = t;
    }
    __syncthreads();
    m = red[0];

    float s = 0.f;
#pragma unroll
    for (int i = 0; i < 16; i++) {
        float4 e;
        e.x = __expf(v[i].x - m);
        e.y = __expf(v[i].y - m);
        e.z = __expf(v[i].z - m);
        e.w = __expf(v[i].w - m);
        s += (e.x + e.y) + (e.z + e.w);
        e4[tid + 256 * i] = e;
    }

    __syncthreads();
#pragma unroll
    for (int off = 16; off; off >>= 1) s += __shfl_xor_sync(0xffffffffu, s, off);
    if ((tid & 31) == 0) red[tid >> 5] = s;
    __syncthreads();
    if (tid == 0) {
        float t = 0.f;
#pragma unroll
        for (int i = 0; i < 8; i++) t += red[i];
        g_inv[row] = 1.0f / t;
    }
}

// ---------------------------------------------------------------------------
__device__ __forceinline__ void cp16(uint32_t saddr, const void* gaddr) {
    asm volatile("cp.async.cg.shared.global [%0], [%1], 16;" :: "r"(saddr), "l"(gaddr));
}
__device__ __forceinline__ void cp_commit() { asm volatile("cp.async.commit_group;"); }
template <int N>
__device__ __forceinline__ void cp_wait() {
    asm volatile("cp.async.wait_group %0;" :: "n"(N));
}

// ---------------------------------------------------------------------------
// Kernel 2: out[b,c,k] = inv[b,k] * sum_s e[b,k,s] * f[b,c,s]
//
// Lane mapping: c_sub = lane>>3 (4 c rows), s_sub = lane&7 (8 s-quads).
// Warp step covers 4 c x 32 s with ONE f LDG.128 (4 full 128B lines, each f
// byte loaded exactly once per CTA) and 19 e LDS.128 (4-way broadcast, 128B
// unique per instr = 1 wavefront). acc = 19 u64 per lane (f32x2 packed).
// 16 warps = 8 c-quads x 2 s-halves; e double-buffered via cp.async.
// ---------------------------------------------------------------------------
__global__ __launch_bounds__(NTHR, 1) void ctx_k(const float* __restrict__ feats,
                                                 float* __restrict__ out) {
    extern __shared__ float es[];                     // [2][K_][SCH]
    const int b     = blockIdx.y;
    const int tid   = threadIdx.x;
    const int lane  = tid & 31;
    const int w     = tid >> 5;                       // 0..15
    const int cq    = w & 7;                          // c-quad
    const int sh    = w >> 3;                         // s-half (0/1)
    const int c_sub = lane >> 3;
    const int s_sub = lane & 7;
    const int c     = blockIdx.x * CT + cq * 4 + c_sub;

    const float* erow = g_e + (size_t)b * K_ * HW_;
    const uint32_t smem_base = (uint32_t)__cvta_generic_to_shared(es);

    // f pointer for this lane: steps advance by 32 s within the s-half
    const char* fptr = (const char*)(feats + ((size_t)b * C_ + c) * HW_
                                     + sh * (SCH / 2) + s_sub * 4);

    u64 acc[K_];
#pragma unroll
    for (int k = 0; k < K_; k++) acc[k] = 0ULL;

    // ---- stage chunk 0 into buffer 0 ----
    {
        const float4* src = (const float4*)erow;
#pragma unroll 1
        for (int idx = tid; idx < K_ * (SCH / 4); idx += NTHR) {
            int k = idx >> 8;
            int j = idx & (SCH / 4 - 1);
            cp16(smem_base + (uint32_t)(idx << 4), src + k * (HW_ / 4) + j);
        }
        cp_commit();
    }

    // ---- f prefetch (distance 2 in step units, continuous across chunks) ----
    ulonglong2 fA = *(const ulonglong2*)(fptr);
    ulonglong2 fB = *(const ulonglong2*)(fptr + 32 * 4);

#pragma unroll 1
    for (int ch = 0; ch < NCHUNK; ch++) {
        __syncthreads();
        if (ch + 1 < NCHUNK) {
            const float4* src = (const float4*)(erow + (ch + 1) * SCH);
            const uint32_t boff = ((ch + 1) & 1) * (K_ * SCH * 4);
#pragma unroll 1
            for (int idx = tid; idx < K_ * (SCH / 4); idx += NTHR) {
                int k = idx >> 8;
                int j = idx & (SCH / 4 - 1);
                cp16(smem_base + boff + (uint32_t)(idx << 4), src + k * (HW_ / 4) + j);
            }
            cp_commit();
            cp_wait<1>();
        } else {
            cp_wait<0>();
        }
        __syncthreads();

        // e base for this warp this chunk: + s_half offset + lane's s_sub quad
        const float* esc = es + ((ch & 1) ? (K_ * SCH) : 0)
                              + sh * (SCH / 2) + s_sub * 4;

#pragma unroll 1
        for (int st = 0; st < STEPS; st++) {
            // global step index for f prefetch addressing
            const int gstep = ch * STEPS + st;
            // prefetch f for step +2. Step +1 crosses within chunk (+32 s);
            // stride between steps is 32 floats, but chunk boundary jumps:
            // flat mapping: s(gstep) = (gstep/16)*1024 + sh*512 + (gstep%16)*32
            int gp = gstep + 2;
            if (gp >= NCHUNK * STEPS) gp = gstep;
            const long long soff =
                (long long)(gp >> 4) * SCH + (gp & 15) * 32;
            const long long soff0 =
                (long long)(gstep >> 4) * SCH + (gstep & 15) * 32;
            ulonglong2 fC = *(const ulonglong2*)(fptr + (soff - 0) * 4
                                                 - 0 * 0 + 0);
            // (fptr already includes sh*512 + s_sub*4; soff is relative base)
            fC = *(const ulonglong2*)(fptr + soff * 4);
            (void)soff0;

            const float* ep = esc + st * 32;

#pragma unroll
            for (int k = 0; k < K_; k++) {
                ulonglong2 ev = *(const ulonglong2*)(ep + k * SCH);
                asm("fma.rn.f32x2 %0, %1, %2, %0;"
                    : "+l"(acc[k]) : "l"(ev.x), "l"(fA.x));
                asm("fma.rn.f32x2 %0, %1, %2, %0;"
                    : "+l"(acc[k]) : "l"(ev.y), "l"(fA.y));
            }
            fA = fB;
            fB = fC;
        }
    }

    // ---- epilogue ----
    // fold u64 halves, reduce over the 8 s_sub lanes (xor 1,2,4)
    __syncthreads();                                  // smem now reusable
    float* part = es;                                 // [2][8][4][K_] floats
#pragma unroll
    for (int k = 0; k < K_; k++) {
        unsigned int lo = (unsigned int)(acc[k] & 0xffffffffULL);
        unsigned int hi = (unsigned int)(acc[k] >> 32);
        float v = __uint_as_float(lo) + __uint_as_float(hi);
        v += __shfl_xor_sync(0xffffffffu, v, 1);
        v += __shfl_xor_sync(0xffffffffu, v, 2);
        v += __shfl_xor_sync(0xffffffffu, v, 4);
        if (s_sub == 0)
            part[((sh * 8 + cq) * 4 + c_sub) * K_ + k] = v;
    }
    __syncthreads();

    const float* invp = g_inv + b * K_;
#pragma unroll 1
    for (int idx = tid; idx < CT * K_; idx += NTHR) {
        int cl = idx / K_;                            // 0..31  (cq*4 + c_sub)
        int k  = idx - cl * K_;
        float v = part[(cl) * K_ + k] + part[(8 * 4 + cl) * K_ + k];
        out[((size_t)b * C_ + blockIdx.x * CT + cl) * K_ + k] = v * invp[k];
    }
}

// ---------------------------------------------------------------------------
extern "C" void kernel_launch(void* const* d_in, const int* in_sizes, int n_in,
                              void* d_out, int out_size) {
    const float* feats = (const float*)d_in[0];   // (8, 512, 128, 128) fp32
    const float* probs = (const float*)d_in[1];   // (8, 19, 128, 128) fp32
    float* out = (float*)d_out;                   // (8, 512, 19, 1) fp32

    cudaFuncSetAttribute(ctx_k, cudaFuncAttributeMaxDynamicSharedMemorySize,
                         SMEM_FLOATS * (int)sizeof(float));

    softmax_k<<<B_ * K_, 256>>>(probs);
    ctx_k<<<dim3(C_ / CT, B_), NTHR, SMEM_FLOATS * sizeof(float)>>>(feats, out);
}

// round 6
// speedup vs baseline: 1.2356x; 1.2356x over previous
#include <cuda_runtime.h>
#include <cstdint>

#define B_   8
#define K_   19
#define C_   512
#define HW_  16384
#define SCH  1024                 // s-chunk per buffer
#define NCHUNK (HW_ / SCH)        // 16
#define IPC  (SCH / 64)           // 16 steps per chunk (64 s each)
#define CC   4                    // c rows per warp (register blocking)
#define CT   32                   // c rows per block
#define NTHR 512                  // 16 warps: wg0 k[0,10), wg1 k[10,19)
#define CHUNK_BYTES (K_ * SCH * 4)   // 77824
#define SMEM_FLOATS (2 * K_ * SCH)

typedef unsigned long long u64;

__device__ __align__(16) float g_e[B_ * K_ * HW_];
__device__ float g_inv[B_ * K_];

// ---------------------------------------------------------------------------
// Kernel 1: e = exp(p - rowmax), inv = 1/sum(e). One block per (b,k) row.
// ---------------------------------------------------------------------------
__global__ __launch_bounds__(256) void softmax_k(const float* __restrict__ probs) {
    const int row = blockIdx.x;
    const float4* p4 = (const float4*)(probs + (size_t)row * HW_);
    float4* e4 = (float4*)(g_e + (size_t)row * HW_);
    const int tid = threadIdx.x;

    float4 v[16];
    float m = -1e30f;
#pragma unroll
    for (int i = 0; i < 16; i++) {
        v[i] = p4[tid + 256 * i];
        m = fmaxf(m, fmaxf(fmaxf(v[i].x, v[i].y), fmaxf(v[i].z, v[i].w)));
    }

    __shared__ float red[32];
#pragma unroll
    for (int off = 16; off; off >>= 1) m = fmaxf(m, __shfl_xor_sync(0xffffffffu, m, off));
    if ((tid & 31) == 0) red[tid >> 5] = m;
    __syncthreads();
    if (tid < 32) {
        float t = (tid < 8) ? red[tid] : -1e30f;
#pragma unroll
        for (int off = 4; off; off >>= 1) t = fmaxf(t, __shfl_xor_sync(0xffffffffu, t, off));
        if (tid == 0) red[0] = t;
    }
    __syncthreads();
    m = red[0];

    float s = 0.f;
#pragma unroll
    for (int i = 0; i < 16; i++) {
        float4 e;
        e.x = __expf(v[i].x - m);
        e.y = __expf(v[i].y - m);
        e.z = __expf(v[i].z - m);
        e.w = __expf(v[i].w - m);
        s += (e.x + e.y) + (e.z + e.w);
        e4[tid + 256 * i] = e;
    }

    __syncthreads();
#pragma unroll
    for (int off = 16; off; off >>= 1) s += __shfl_xor_sync(0xffffffffu, s, off);
    if ((tid & 31) == 0) red[tid >> 5] = s;
    __syncthreads();
    if (tid == 0) {
        float t = 0.f;
#pragma unroll
        for (int i = 0; i < 8; i++) t += red[i];
        g_inv[row] = 1.0f / t;
    }
}

// ---------------------------------------------------------------------------
// mbarrier / bulk-copy helpers
// ---------------------------------------------------------------------------
__device__ __forceinline__ void mbar_init(uint32_t addr, uint32_t cnt) {
    asm volatile("mbarrier.init.shared.b64 [%0], %1;" :: "r"(addr), "r"(cnt) : "memory");
}
__device__ __forceinline__ void mbar_expect_tx(uint32_t addr, uint32_t bytes) {
    asm volatile("mbarrier.arrive.expect_tx.shared.b64 _, [%0], %1;"
                 :: "r"(addr), "r"(bytes) : "memory");
}
__device__ __forceinline__ void mbar_wait(uint32_t addr, uint32_t parity) {
    asm volatile(
        "{\n\t"
        ".reg .pred P;\n\t"
        "WAITL_%=:\n\t"
        "mbarrier.try_wait.parity.acquire.cta.shared::cta.b64 P, [%0], %1, 0x989680;\n\t"
        "@P bra.uni WAITD_%=;\n\t"
        "bra.uni WAITL_%=;\n\t"
        "WAITD_%=:\n\t"
        "}"
        :: "r"(addr), "r"(parity) : "memory");
}
__device__ __forceinline__ void bulk_g2s(uint32_t dst, const void* src,
                                         uint32_t bytes, uint32_t mbar) {
    asm volatile(
        "cp.async.bulk.shared::cluster.global.mbarrier::complete_tx::bytes "
        "[%0], [%1], %2, [%3];"
        :: "r"(dst), "l"(src), "r"(bytes), "r"(mbar) : "memory");
}

// one k-group's FMA work for a 64-s strip
template <int KN, int KOFF>
__device__ __forceinline__ void fma_block(const float* ep, u64 (&acc)[10][CC],
                                          const u64 (&f)[CC]) {
#pragma unroll
    for (int j = 0; j < KN; j++) {
        u64 e2 = *(const u64*)(ep + (KOFF + j) * SCH);
#pragma unroll
        for (int cc = 0; cc < CC; cc++)
            asm("fma.rn.f32x2 %0, %1, %2, %0;"
                : "+l"(acc[j][cc]) : "l"(e2), "l"(f[cc]));
    }
}

// ---------------------------------------------------------------------------
// Kernel 2: out[b,c,k] = inv[b,k] * sum_s e[b,k,s] * f[b,c,s]
//   - e double-buffered in smem via cp.async.bulk (19 x 4KB per chunk, one
//     issuing thread, mbarrier completion) -> no per-16B LDGSTS issue tax
//   - warps 0-7 cover k 0..9, warps 8-15 cover k 10..18 (acc fits 128 regs)
//   - f streamed with distance-2 prefetch, step-pair unroll (no rotation MOVs)
//   - packed fma.rn.f32x2 accumulators
// ---------------------------------------------------------------------------
__global__ __launch_bounds__(NTHR, 1) void ctx_k(const float* __restrict__ feats,
                                                 float* __restrict__ out) {
    extern __shared__ float es[];                     // [2][K_][SCH]
    __shared__ __align__(8) u64 mbar[2];

    const int b    = blockIdx.y;
    const int tid  = threadIdx.x;
    const int lane = tid & 31;
    const int w    = tid >> 5;
    const int wg   = w >> 3;
    const int wl   = w & 7;
    const int c0   = blockIdx.x * CT + wl * CC;

    const float* erow = g_e + (size_t)b * K_ * HW_;
    const uint32_t smem_base = (uint32_t)__cvta_generic_to_shared(es);
    const uint32_t mbar0 = (uint32_t)__cvta_generic_to_shared(&mbar[0]);

    const u64* fbase = (const u64*)(feats + ((size_t)b * C_ + c0) * HW_) + lane;

    u64 acc[10][CC];
#pragma unroll
    for (int k = 0; k < 10; k++)
#pragma unroll
        for (int cc = 0; cc < CC; cc++) acc[k][cc] = 0ULL;

    if (tid == 0) {
        mbar_init(mbar0, 1);
        mbar_init(mbar0 + 8, 1);
    }
    __syncthreads();

    // ---- stage chunk 0 into buffer 0 ----
    if (tid == 0) {
        mbar_expect_tx(mbar0, CHUNK_BYTES);
#pragma unroll 1
        for (int k = 0; k < K_; k++)
            bulk_g2s(smem_base + k * (SCH * 4), erow + (size_t)k * HW_,
                     SCH * 4, mbar0);
    }

    // ---- f prefetch: steps advance 64 s = 32 u64; distance 2 ----
    u64 f0[CC], f1[CC];
#pragma unroll
    for (int cc = 0; cc < CC; cc++) f0[cc] = fbase[cc * (HW_ / 2)];
#pragma unroll
    for (int cc = 0; cc < CC; cc++) f1[cc] = fbase[cc * (HW_ / 2) + 32];

#pragma unroll 1
    for (int ch = 0; ch < NCHUNK; ch++) {
        // stage chunk ch+1 (its buffer was retired at end of chunk ch-1)
        if (tid == 0 && ch + 1 < NCHUNK) {
            const uint32_t mb = mbar0 + ((ch + 1) & 1) * 8;
            const uint32_t dst = smem_base + ((ch + 1) & 1) * CHUNK_BYTES;
            const float* src = erow + (ch + 1) * SCH;
            mbar_expect_tx(mb, CHUNK_BYTES);
#pragma unroll 1
            for (int k = 0; k < K_; k++)
                bulk_g2s(dst + k * (SCH * 4), src + (size_t)k * HW_,
                         SCH * 4, mb);
        }

        // wait for chunk ch's buffer
        mbar_wait(mbar0 + (ch & 1) * 8, (ch >> 1) & 1);
        __syncthreads();

        const float* esc = es + (ch & 1) * (K_ * SCH) + lane * 2;

#pragma unroll 1
        for (int st = 0; st < IPC; st += 2) {
            const int g = ch * IPC + st;

            if (wg == 0) fma_block<10, 0>(esc + st * 64, acc, f0);
            else         fma_block<9, 10>(esc + st * 64, acc, f0);
            {   // reload f0 for step g+2 (after last read; WAR via scoreboard)
                const int gp = (g + 2 < NCHUNK * IPC) ? (g + 2) : g;
#pragma unroll
                for (int cc = 0; cc < CC; cc++)
                    f0[cc] = fbase[cc * (HW_ / 2) + gp * 32];
            }

            if (wg == 0) fma_block<10, 0>(esc + (st + 1) * 64, acc, f1);
            else         fma_block<9, 10>(esc + (st + 1) * 64, acc, f1);
            {   // reload f1 for step g+3
                const int gp = (g + 3 < NCHUNK * IPC) ? (g + 3) : g;
#pragma unroll
                for (int cc = 0; cc < CC; cc++)
                    f1[cc] = fbase[cc * (HW_ / 2) + gp * 32];
            }
        }
        __syncthreads();    // all warps done with buffer (ch&1) before restage
    }

    // ---- epilogue: fold packed halves, warp-reduce over s-lanes, store ----
    const int koff = wg * 10;
    const int kn   = wg ? 9 : 10;
    const float* invp = g_inv + b * K_;
    float* orow = out + ((size_t)b * C_ + c0) * K_;
#pragma unroll
    for (int j = 0; j < 10; j++) {
        if (j >= kn) break;
#pragma unroll
        for (int cc = 0; cc < CC; cc++) {
            unsigned int lo = (unsigned int)(acc[j][cc] & 0xffffffffULL);
            unsigned int hi = (unsigned int)(acc[j][cc] >> 32);
            float v = __uint_as_float(lo) + __uint_as_float(hi);
#pragma unroll
            for (int off = 16; off; off >>= 1)
                v += __shfl_xor_sync(0xffffffffu, v, off);
            if (lane == 0)
                orow[cc * K_ + koff + j] = v * invp[koff + j];
        }
    }
}

// ---------------------------------------------------------------------------
extern "C" void kernel_launch(void* const* d_in, const int* in_sizes, int n_in,
                              void* d_out, int out_size) {
    const float* feats = (const float*)d_in[0];   // (8, 512, 128, 128) fp32
    const float* probs = (const float*)d_in[1];   // (8, 19, 128, 128) fp32
    float* out = (float*)d_out;                   // (8, 512, 19, 1) fp32

    cudaFuncSetAttribute(ctx_k, cudaFuncAttributeMaxDynamicSharedMemorySize,
                         SMEM_FLOATS * (int)sizeof(float));

    softmax_k<<<B_ * K_, 256>>>(probs);
    ctx_k<<<dim3(C_ / CT, B_), NTHR, SMEM_FLOATS * sizeof(float)>>>(feats, out);
}